// round 1
// baseline (speedup 1.0000x reference)
#include <cuda_runtime.h>
#include <cuda_bf16.h>
#include <math.h>

#define T_STEPS 32
#define BATCH   8192
#define MDIM    4
#define NDIM    2
#define H1      480
#define HID     200
#define H2      320

// ---------------- scratch (device globals; no allocation allowed) ----------
__device__ float g_a1  [BATCH * H1];        // 15.7 MB
__device__ float g_gx  [BATCH * 3 * HID];   // 19.7 MB
__device__ float g_gh  [BATCH * 3 * HID];   // 19.7 MB
__device__ float g_a2  [BATCH * H2];        // 10.5 MB
__device__ float g_hn  [2 * BATCH * HID];   // 13.1 MB (ping-pong)
__device__ float g_prior[BATCH * MDIM];
__device__ float g_post [BATCH * MDIM];
__device__ float g_dm1y [BATCH * NDIM];

// ---------------- init: copy hn0, zero prior/post ---------------------------
__global__ void init_kernel(const float* __restrict__ hn0,
                            float* __restrict__ hn,
                            float* __restrict__ prior,
                            float* __restrict__ post) {
    int i = blockIdx.x * blockDim.x + threadIdx.x;
    if (i < BATCH * HID) hn[i] = hn0[i];
    if (i < BATCH * MDIM) { prior[i] = 0.f; post[i] = 0.f; }
}

// ---------------- kernel 1: filter algebra + features + a1 ------------------
// block: 256 threads, handles 64 batch rows.
__global__ void feat_a1_kernel(const float* __restrict__ y_t,   // [B,2]
                               const float* __restrict__ F,     // [4,4]
                               const float* __restrict__ Hm,    // [2,4]
                               const float* __restrict__ W1,    // [8,480]
                               const float* __restrict__ b1,    // [480]
                               const float* __restrict__ post,  // [B,4] (prev)
                               float* __restrict__ prior,       // [B,4] in/out
                               float* __restrict__ dm1y_out,    // [B,2]
                               float* __restrict__ a1) {        // [B,480]
    __shared__ float feat[64][9];
    int tid = threadIdx.x;
    int b0 = blockIdx.x * 64;
    if (tid < 64) {
        int b = b0 + tid;
        float p[4], pr_old[4];
        #pragma unroll
        for (int m = 0; m < 4; m++) { p[m] = post[b*4+m]; pr_old[m] = prior[b*4+m]; }
        // new prior = F @ post
        float pn[4];
        #pragma unroll
        for (int i = 0; i < 4; i++) {
            float s = 0.f;
            #pragma unroll
            for (int j = 0; j < 4; j++) s += __ldg(&F[i*4+j]) * p[j];
            pn[i] = s;
        }
        // m1y = Hm @ prior
        float my[2];
        #pragma unroll
        for (int i = 0; i < 2; i++) {
            float s = 0.f;
            #pragma unroll
            for (int j = 0; j < 4; j++) s += __ldg(&Hm[i*4+j]) * pn[j];
            my[i] = s;
        }
        float dy0 = y_t[b*2+0] - my[0];
        float dy1 = y_t[b*2+1] - my[1];
        dm1y_out[b*2+0] = dy0;
        dm1y_out[b*2+1] = dy1;
        float inv_y = rsqrtf(fmaxf(dy0*dy0 + dy1*dy1, 1e-12f));
        feat[tid][0] = dy0*inv_y; feat[tid][1] = dy1*inv_y;
        feat[tid][2] = dy0*inv_y; feat[tid][3] = dy1*inv_y;
        float d[4], s2 = 0.f;
        #pragma unroll
        for (int m = 0; m < 4; m++) { d[m] = p[m] - pr_old[m]; s2 += d[m]*d[m]; }
        float inv_x = rsqrtf(fmaxf(s2, 1e-12f));
        #pragma unroll
        for (int m = 0; m < 4; m++) feat[tid][4+m] = d[m]*inv_x;
        // commit new prior
        #pragma unroll
        for (int m = 0; m < 4; m++) prior[b*4+m] = pn[m];
    }
    __syncthreads();
    // a1 = relu(feat @ W1 + b1)   (K=8)
    for (int idx = tid; idx < 64 * H1; idx += 256) {
        int r = idx / H1, c = idx % H1;
        float s = __ldg(&b1[c]);
        #pragma unroll
        for (int k = 0; k < 8; k++) s += feat[r][k] * __ldg(&W1[k*H1 + c]);
        a1[(b0 + r)*H1 + c] = fmaxf(s, 0.f);
    }
}

// ---------------- tiled fp32 GEMM: C = act(A[MxK] @ B[KxN] + bias) ----------
// BM=128, BN=64, BK=8, 256 threads, per-thread 8x4. K%8==0, M%128==0 assumed.
template<int ACT>
__global__ void gemm_kernel(const float* __restrict__ A,
                            const float* __restrict__ B,
                            const float* __restrict__ bias,
                            float* __restrict__ C,
                            int M, int N, int K) {
    __shared__ float As[8][128];
    __shared__ float Bs[8][64];
    int tid = threadIdx.x;
    int bm = blockIdx.y * 128;
    int bn = blockIdx.x * 64;
    int tx = tid % 16;     // N dir, 4 cols each
    int ty = tid / 16;     // M dir, 8 rows each
    float acc[8][4];
    #pragma unroll
    for (int i = 0; i < 8; i++)
        #pragma unroll
        for (int j = 0; j < 4; j++) acc[i][j] = 0.f;

    int a_row = tid >> 1;            // 0..127
    int a_col = (tid & 1) * 4;       // 0 or 4
    int b_row = tid >> 4;            // 0..15 (only tid<128 used -> 0..7)
    int b_col = (tid & 15) * 4;      // 0..60

    for (int k0 = 0; k0 < K; k0 += 8) {
        float4 av = *(const float4*)(A + (size_t)(bm + a_row)*K + k0 + a_col);
        As[a_col+0][a_row] = av.x;
        As[a_col+1][a_row] = av.y;
        As[a_col+2][a_row] = av.z;
        As[a_col+3][a_row] = av.w;
        if (tid < 128) {
            int col = bn + b_col;
            float4 bv = make_float4(0.f,0.f,0.f,0.f);
            if (col < N) bv = *(const float4*)(B + (size_t)(k0 + b_row)*N + col);
            *(float4*)&Bs[b_row][b_col] = bv;
        }
        __syncthreads();
        #pragma unroll
        for (int k = 0; k < 8; k++) {
            float a_frag[8], b_frag[4];
            *(float4*)&a_frag[0] = *(const float4*)&As[k][ty*8];
            *(float4*)&a_frag[4] = *(const float4*)&As[k][ty*8 + 4];
            *(float4*)&b_frag[0] = *(const float4*)&Bs[k][tx*4];
            #pragma unroll
            for (int i = 0; i < 8; i++)
                #pragma unroll
                for (int j = 0; j < 4; j++)
                    acc[i][j] = fmaf(a_frag[i], b_frag[j], acc[i][j]);
        }
        __syncthreads();
    }
    #pragma unroll
    for (int j = 0; j < 4; j++) {
        int col = bn + tx*4 + j;
        if (col >= N) continue;
        float bv = __ldg(&bias[col]);
        #pragma unroll
        for (int i = 0; i < 8; i++) {
            int row = bm + ty*8 + i;
            float v = acc[i][j] + bv;
            if (ACT == 1) v = fmaxf(v, 0.f);
            C[(size_t)row*N + col] = v;
        }
    }
}

// ---------------- GRU gate combine ------------------------------------------
__global__ void gru_gate_kernel(const float* __restrict__ Gx,
                                const float* __restrict__ Gh,
                                const float* __restrict__ h_in,
                                float* __restrict__ h_out) {
    int idx = blockIdx.x * blockDim.x + threadIdx.x;
    if (idx >= BATCH * HID) return;
    int b = idx / HID, j = idx % HID;
    const float* gx = Gx + (size_t)b * 3 * HID;
    const float* gh = Gh + (size_t)b * 3 * HID;
    float z = 1.f / (1.f + __expf(-(gx[j]           + gh[j])));
    float r = 1.f / (1.f + __expf(-(gx[j + HID]     + gh[j + HID])));
    float hc = tanhf(gx[j + 2*HID] + r * gh[j + 2*HID]);
    float h = h_in[idx];
    h_out[idx] = z * h + (1.f - z) * hc;
}

// ---------------- gain head + innovation + posterior ------------------------
// 256 threads = 32 rows x 8-thread teams.
__global__ void out_kernel(const float* __restrict__ a2,    // [B,320]
                           const float* __restrict__ W3,    // [320,8]
                           const float* __restrict__ b3,    // [8]
                           const float* __restrict__ dm1y,  // [B,2]
                           const float* __restrict__ prior, // [B,4]
                           float* __restrict__ post,        // [B,4]
                           float* __restrict__ out_t) {     // [B,4]
    int tid = threadIdx.x;
    int lane = tid & 7;
    int b = blockIdx.x * 32 + (tid >> 3);
    float kg[8];
    #pragma unroll
    for (int o = 0; o < 8; o++) kg[o] = 0.f;
    const float* arow = a2 + (size_t)b * H2;
    for (int k = lane; k < H2; k += 8) {
        float a = arow[k];
        float4 w0 = *(const float4*)(W3 + k*8);
        float4 w1 = *(const float4*)(W3 + k*8 + 4);
        kg[0] = fmaf(a, w0.x, kg[0]); kg[1] = fmaf(a, w0.y, kg[1]);
        kg[2] = fmaf(a, w0.z, kg[2]); kg[3] = fmaf(a, w0.w, kg[3]);
        kg[4] = fmaf(a, w1.x, kg[4]); kg[5] = fmaf(a, w1.y, kg[5]);
        kg[6] = fmaf(a, w1.z, kg[6]); kg[7] = fmaf(a, w1.w, kg[7]);
    }
    #pragma unroll
    for (int off = 4; off > 0; off >>= 1)
        #pragma unroll
        for (int o = 0; o < 8; o++)
            kg[o] += __shfl_down_sync(0xFFFFFFFFu, kg[o], off, 8);
    if (lane == 0) {
        float dy0 = dm1y[b*2+0], dy1 = dm1y[b*2+1];
        #pragma unroll
        for (int m = 0; m < 4; m++) {
            float k0 = kg[2*m]   + __ldg(&b3[2*m]);
            float k1 = kg[2*m+1] + __ldg(&b3[2*m+1]);
            float pv = prior[b*4+m] + k0*dy0 + k1*dy1;
            post[b*4+m] = pv;
            out_t[b*4+m] = pv;
        }
    }
}

// ---------------- launch ----------------------------------------------------
extern "C" void kernel_launch(void* const* d_in, const int* in_sizes, int n_in,
                              void* d_out, int out_size) {
    const float* y   = (const float*)d_in[0];   // [T,B,2]
    const float* F   = (const float*)d_in[1];   // [4,4]
    const float* Hm  = (const float*)d_in[2];   // [2,4]
    const float* W1  = (const float*)d_in[3];   // [8,480]
    const float* b1  = (const float*)d_in[4];
    const float* Wg  = (const float*)d_in[5];   // [480,600]
    const float* Ug  = (const float*)d_in[6];   // [200,600]
    const float* bg  = (const float*)d_in[7];   // [2,600]
    const float* W2  = (const float*)d_in[8];   // [200,320]
    const float* b2  = (const float*)d_in[9];
    const float* W3  = (const float*)d_in[10];  // [320,8]
    const float* b3  = (const float*)d_in[11];
    const float* hn0 = (const float*)d_in[12];  // [B,200]
    float* out = (float*)d_out;                 // [T,B,4]

    float *a1, *gx, *gh, *a2, *hn, *prior, *post, *dm1y;
    cudaGetSymbolAddress((void**)&a1,   g_a1);
    cudaGetSymbolAddress((void**)&gx,   g_gx);
    cudaGetSymbolAddress((void**)&gh,   g_gh);
    cudaGetSymbolAddress((void**)&a2,   g_a2);
    cudaGetSymbolAddress((void**)&hn,   g_hn);
    cudaGetSymbolAddress((void**)&prior,g_prior);
    cudaGetSymbolAddress((void**)&post, g_post);
    cudaGetSymbolAddress((void**)&dm1y, g_dm1y);

    init_kernel<<<(BATCH*HID + 255)/256, 256>>>(hn0, hn, prior, post);

    for (int t = 0; t < T_STEPS; t++) {
        const float* hin = hn + (size_t)(t & 1) * BATCH * HID;
        float* hout      = hn + (size_t)((t + 1) & 1) * BATCH * HID;

        feat_a1_kernel<<<BATCH/64, 256>>>(y + (size_t)t*BATCH*NDIM, F, Hm, W1, b1,
                                          post, prior, dm1y, a1);

        gemm_kernel<0><<<dim3((3*HID + 63)/64, BATCH/128), 256>>>(
            a1, Wg, bg,       gx, BATCH, 3*HID, H1);
        gemm_kernel<0><<<dim3((3*HID + 63)/64, BATCH/128), 256>>>(
            hin, Ug, bg + 3*HID, gh, BATCH, 3*HID, HID);

        gru_gate_kernel<<<(BATCH*HID + 255)/256, 256>>>(gx, gh, hin, hout);

        gemm_kernel<1><<<dim3((H2 + 63)/64, BATCH/128), 256>>>(
            hout, W2, b2, a2, BATCH, H2, HID);

        out_kernel<<<BATCH/32, 256>>>(a2, W3, b3, dm1y, prior, post,
                                      out + (size_t)t*BATCH*MDIM);
    }
}

// round 4
// speedup vs baseline: 1.9068x; 1.9068x over previous
#include <cuda_runtime.h>
#include <cuda_bf16.h>
#include <cstdint>
#include <math.h>

#define T_STEPS 32
#define BATCH   8192
#define MDIM    4
#define NDIM    2
#define H1      480
#define HID     200
#define H2      320

// ---------------- scratch (device globals; no allocation allowed) -----------
__device__ float g_gx  [BATCH * 3 * HID];
__device__ float g_gh  [BATCH * 3 * HID];
__device__ float g_a2  [BATCH * H2];
__device__ float g_hn  [2 * BATCH * HID];
__device__ float g_prior[BATCH * MDIM];
__device__ float g_post [BATCH * MDIM];
__device__ float g_dm1y [BATCH * NDIM];
// split-bf16 planes (hi/lo)
__device__ __nv_bfloat16 g_a1h[BATCH * H1],  g_a1l[BATCH * H1];
__device__ __nv_bfloat16 g_hnh[BATCH * HID], g_hnl[BATCH * HID];
__device__ __nv_bfloat16 g_WgTh[3*HID*H1],  g_WgTl[3*HID*H1];
__device__ __nv_bfloat16 g_UgTh[3*HID*HID], g_UgTl[3*HID*HID];
__device__ __nv_bfloat16 g_W2Th[H2*HID],    g_W2Tl[H2*HID];

// ---------------- PTX helpers ------------------------------------------------
__device__ __forceinline__ uint32_t smem_u32(const void* p) {
    uint32_t a;
    asm("{ .reg .u64 t; cvta.to.shared.u64 t, %1; cvt.u32.u64 %0, t; }" : "=r"(a) : "l"(p));
    return a;
}
__device__ __forceinline__ void cp16(uint32_t dst, const void* src) {
    asm volatile("cp.async.cg.shared.global [%0], [%1], 16;" :: "r"(dst), "l"(src) : "memory");
}
__device__ __forceinline__ void sts_zero16(uint32_t addr) {
    asm volatile("st.shared.v4.b32 [%0], {%1,%1,%1,%1};" :: "r"(addr), "r"(0) : "memory");
}
__device__ __forceinline__ void ldsm4(uint32_t* r, uint32_t addr) {
    asm volatile("ldmatrix.sync.aligned.m8n8.x4.shared.b16 {%0,%1,%2,%3}, [%4];"
                 : "=r"(r[0]), "=r"(r[1]), "=r"(r[2]), "=r"(r[3]) : "r"(addr));
}
__device__ __forceinline__ void mma16816(float* c, const uint32_t* a, uint32_t b0, uint32_t b1) {
    asm volatile("mma.sync.aligned.m16n8k16.row.col.f32.bf16.bf16.f32 "
                 "{%0,%1,%2,%3}, {%4,%5,%6,%7}, {%8,%9}, {%0,%1,%2,%3};"
                 : "+f"(c[0]), "+f"(c[1]), "+f"(c[2]), "+f"(c[3])
                 : "r"(a[0]), "r"(a[1]), "r"(a[2]), "r"(a[3]), "r"(b0), "r"(b1));
}

// ---------------- split-bf16 HMMA GEMM ---------------------------------------
// C[128 x 64 tile] = (Ah+Al)[M x K] @ (Bh+Bl)^T[N x K] + bias, fp32 out.
// BK=32, 256 threads, 8 warps (4 m x 2 n), warp tile 32x32, double-buffered cp.async.
// smem stage: Ah(128x40h) Al Bh(64x40h) Bl  (row stride 80B, 16B pad -> conflict-free ldmatrix)
#define ROWB   80
#define A_PL   (128 * ROWB)          // 10240
#define B_PL   (64 * ROWB)           // 5120
#define STAGE  (2 * A_PL + 2 * B_PL) // 30720

template<bool RELU>
__global__ __launch_bounds__(256, 2)
void gemm_mma(const __nv_bfloat16* __restrict__ Ah, const __nv_bfloat16* __restrict__ Al,
              const __nv_bfloat16* __restrict__ Bh, const __nv_bfloat16* __restrict__ Bl,
              const float* __restrict__ bias, float* __restrict__ C,
              int Ncols, int K) {
    extern __shared__ char smem[];
    const uint32_t s0 = smem_u32(smem);
    const int tid  = threadIdx.x;
    const int lane = tid & 31, wid = tid >> 5;
    const int wm = (wid & 3) * 32;        // warp m offset in tile
    const int wn = (wid >> 2) * 32;       // warp n offset in tile
    const int bm = blockIdx.y * 128;
    const int bn = blockIdx.x * 64;

    float acc[2][4][4];
    #pragma unroll
    for (int i = 0; i < 2; i++)
        #pragma unroll
        for (int j = 0; j < 4; j++)
            #pragma unroll
            for (int k = 0; k < 4; k++) acc[i][j][k] = 0.f;

    const int NC = (K + 31) / 32;

    // ---- stage loader ----
    auto load_stage = [&](int s) {
        uint32_t base = s0 + (uint32_t)(s & 1) * STAGE;
        int k0 = s * 32;
        int kc = K - k0; if (kc > 32) kc = 32;
        #pragma unroll
        for (int it = 0; it < 4; it++) {          // A: 2 planes * 128 rows * 4 chunks
            int idx = tid + it * 256;
            int plane = idx >> 9, r = (idx >> 2) & 127, ch = idx & 3;
            uint32_t dst = base + (uint32_t)plane * A_PL + (uint32_t)r * ROWB + (uint32_t)ch * 16;
            if (ch * 8 < kc)
                cp16(dst, (plane ? Al : Ah) + (size_t)(bm + r) * K + k0 + ch * 8);
            else
                sts_zero16(dst);
        }
        #pragma unroll
        for (int it = 0; it < 2; it++) {          // B: 2 planes * 64 rows * 4 chunks
            int idx = tid + it * 256;
            int plane = idx >> 8, r = (idx >> 2) & 63, ch = idx & 3;
            uint32_t dst = base + 2 * A_PL + (uint32_t)plane * B_PL
                         + (uint32_t)r * ROWB + (uint32_t)ch * 16;
            if ((bn + r) < Ncols && ch * 8 < kc)
                cp16(dst, (plane ? Bl : Bh) + (size_t)(bn + r) * K + k0 + ch * 8);
            else
                sts_zero16(dst);
        }
        asm volatile("cp.async.commit_group;" ::: "memory");
    };

    load_stage(0);

    // ldmatrix lane addressing (within a 16x16 A block / 16x16 B block)
    const uint32_t a_lrow = (uint32_t)(lane & 15) * ROWB + (uint32_t)(lane >> 4) * 16;
    const uint32_t b_lrow = (uint32_t)((lane & 7) + ((lane >> 3) & 1) * 8) * ROWB
                          + (uint32_t)(lane >> 4) * 16;

    for (int i = 0; i < NC; i++) {
        if (i + 1 < NC) {
            load_stage(i + 1);
            asm volatile("cp.async.wait_group 1;" ::: "memory");
        } else {
            asm volatile("cp.async.wait_group 0;" ::: "memory");
        }
        __syncthreads();

        uint32_t base = s0 + (uint32_t)(i & 1) * STAGE;
        uint32_t sAh = base, sAl = base + A_PL;
        uint32_t sBh = base + 2 * A_PL, sBl = sBh + B_PL;

        #pragma unroll
        for (int ks = 0; ks < 2; ks++) {
            uint32_t koff = (uint32_t)ks * 32;            // 16 halves = 32B
            uint32_t ah[2][4], al[2][4], bh[2][4], bl[2][4];
            #pragma unroll
            for (int fm = 0; fm < 2; fm++) {
                uint32_t ro = (uint32_t)(wm + fm * 16) * ROWB + koff + a_lrow;
                ldsm4(ah[fm], sAh + ro);
                ldsm4(al[fm], sAl + ro);
            }
            #pragma unroll
            for (int np = 0; np < 2; np++) {
                uint32_t ro = (uint32_t)(wn + np * 16) * ROWB + koff + b_lrow;
                ldsm4(bh[np], sBh + ro);
                ldsm4(bl[np], sBl + ro);
            }
            #pragma unroll
            for (int fm = 0; fm < 2; fm++)
                #pragma unroll
                for (int j = 0; j < 4; j++) {
                    int np = j >> 1, sel = j & 1;
                    mma16816(acc[fm][j], ah[fm], bh[np][sel], bh[np][sel + 2]);
                    mma16816(acc[fm][j], al[fm], bh[np][sel], bh[np][sel + 2]);
                    mma16816(acc[fm][j], ah[fm], bl[np][sel], bl[np][sel + 2]);
                }
        }
        __syncthreads();
    }

    // ---- epilogue: bias (+relu), direct float2 stores ----
    const int qid = lane >> 2, qt = lane & 3;
    #pragma unroll
    for (int fm = 0; fm < 2; fm++) {
        int row = bm + wm + fm * 16 + qid;
        #pragma unroll
        for (int j = 0; j < 4; j++) {
            int col = bn + wn + j * 8 + qt * 2;
            if (col >= Ncols) continue;
            float b0 = __ldg(&bias[col]), b1 = __ldg(&bias[col + 1]);
            float2 v0 = make_float2(acc[fm][j][0] + b0, acc[fm][j][1] + b1);
            float2 v1 = make_float2(acc[fm][j][2] + b0, acc[fm][j][3] + b1);
            if (RELU) {
                v0.x = fmaxf(v0.x, 0.f); v0.y = fmaxf(v0.y, 0.f);
                v1.x = fmaxf(v1.x, 0.f); v1.y = fmaxf(v1.y, 0.f);
            }
            *(float2*)&C[(size_t)row * Ncols + col]       = v0;
            *(float2*)&C[(size_t)(row + 8) * Ncols + col] = v1;
        }
    }
}

// ---------------- small kernels ---------------------------------------------
__device__ __forceinline__ void split_store(float v, __nv_bfloat16* hi, __nv_bfloat16* lo,
                                            size_t idx) {
    __nv_bfloat16 h = __float2bfloat16(v);
    hi[idx] = h;
    lo[idx] = __float2bfloat16(v - __bfloat162float(h));
}

__global__ void init_kernel(const float* __restrict__ hn0, float* __restrict__ hn,
                            __nv_bfloat16* __restrict__ hnh, __nv_bfloat16* __restrict__ hnl,
                            float* __restrict__ prior, float* __restrict__ post) {
    int i = blockIdx.x * blockDim.x + threadIdx.x;
    if (i < BATCH * HID) {
        float v = hn0[i];
        hn[i] = v;
        split_store(v, hnh, hnl, i);
    }
    if (i < BATCH * MDIM) { prior[i] = 0.f; post[i] = 0.f; }
}

// transpose + split weights: in [K x N] -> planes [N x K]
__global__ void wsplit_kernel(const float* __restrict__ in,
                              __nv_bfloat16* __restrict__ oh, __nv_bfloat16* __restrict__ ol,
                              int K, int N) {
    int i = blockIdx.x * blockDim.x + threadIdx.x;
    if (i < K * N) {
        int k = i / N, n = i % N;
        split_store(in[i], oh, ol, (size_t)n * K + k);
    }
}

__global__ void feat_a1_kernel(const float* __restrict__ y_t,
                               const float* __restrict__ F, const float* __restrict__ Hm,
                               const float* __restrict__ W1, const float* __restrict__ b1,
                               const float* __restrict__ post, float* __restrict__ prior,
                               float* __restrict__ dm1y_out,
                               __nv_bfloat16* __restrict__ a1h,
                               __nv_bfloat16* __restrict__ a1l) {
    __shared__ float feat[64][9];
    int tid = threadIdx.x;
    int b0 = blockIdx.x * 64;
    if (tid < 64) {
        int b = b0 + tid;
        float p[4], pr_old[4];
        #pragma unroll
        for (int m = 0; m < 4; m++) { p[m] = post[b*4+m]; pr_old[m] = prior[b*4+m]; }
        float pn[4];
        #pragma unroll
        for (int i = 0; i < 4; i++) {
            float s = 0.f;
            #pragma unroll
            for (int j = 0; j < 4; j++) s += __ldg(&F[i*4+j]) * p[j];
            pn[i] = s;
        }
        float my[2];
        #pragma unroll
        for (int i = 0; i < 2; i++) {
            float s = 0.f;
            #pragma unroll
            for (int j = 0; j < 4; j++) s += __ldg(&Hm[i*4+j]) * pn[j];
            my[i] = s;
        }
        float dy0 = y_t[b*2+0] - my[0];
        float dy1 = y_t[b*2+1] - my[1];
        dm1y_out[b*2+0] = dy0;
        dm1y_out[b*2+1] = dy1;
        float inv_y = rsqrtf(fmaxf(dy0*dy0 + dy1*dy1, 1e-12f));
        feat[tid][0] = dy0*inv_y; feat[tid][1] = dy1*inv_y;
        feat[tid][2] = dy0*inv_y; feat[tid][3] = dy1*inv_y;
        float d[4], s2 = 0.f;
        #pragma unroll
        for (int m = 0; m < 4; m++) { d[m] = p[m] - pr_old[m]; s2 += d[m]*d[m]; }
        float inv_x = rsqrtf(fmaxf(s2, 1e-12f));
        #pragma unroll
        for (int m = 0; m < 4; m++) feat[tid][4+m] = d[m]*inv_x;
        #pragma unroll
        for (int m = 0; m < 4; m++) prior[b*4+m] = pn[m];
    }
    __syncthreads();
    for (int idx = tid; idx < 64 * H1; idx += 256) {
        int r = idx / H1, c = idx % H1;
        float s = __ldg(&b1[c]);
        #pragma unroll
        for (int k = 0; k < 8; k++) s += feat[r][k] * __ldg(&W1[k*H1 + c]);
        split_store(fmaxf(s, 0.f), a1h, a1l, (size_t)(b0 + r) * H1 + c);
    }
}

__global__ void gru_gate_kernel(const float* __restrict__ Gx, const float* __restrict__ Gh,
                                const float* __restrict__ h_in, float* __restrict__ h_out,
                                __nv_bfloat16* __restrict__ hnh,
                                __nv_bfloat16* __restrict__ hnl) {
    int idx = blockIdx.x * blockDim.x + threadIdx.x;
    if (idx >= BATCH * HID) return;
    int b = idx / HID, j = idx % HID;
    const float* gx = Gx + (size_t)b * 3 * HID;
    const float* gh = Gh + (size_t)b * 3 * HID;
    float z = 1.f / (1.f + __expf(-(gx[j]       + gh[j])));
    float r = 1.f / (1.f + __expf(-(gx[j + HID] + gh[j + HID])));
    float hc = tanhf(gx[j + 2*HID] + r * gh[j + 2*HID]);
    float h = h_in[idx];
    float v = z * h + (1.f - z) * hc;
    h_out[idx] = v;
    split_store(v, hnh, hnl, idx);
}

__global__ void out_kernel(const float* __restrict__ a2, const float* __restrict__ W3,
                           const float* __restrict__ b3, const float* __restrict__ dm1y,
                           const float* __restrict__ prior, float* __restrict__ post,
                           float* __restrict__ out_t) {
    int tid = threadIdx.x;
    int lane = tid & 7;
    int b = blockIdx.x * 32 + (tid >> 3);
    float kg[8];
    #pragma unroll
    for (int o = 0; o < 8; o++) kg[o] = 0.f;
    const float* arow = a2 + (size_t)b * H2;
    for (int k = lane; k < H2; k += 8) {
        float a = arow[k];
        float4 w0 = *(const float4*)(W3 + k*8);
        float4 w1 = *(const float4*)(W3 + k*8 + 4);
        kg[0] = fmaf(a, w0.x, kg[0]); kg[1] = fmaf(a, w0.y, kg[1]);
        kg[2] = fmaf(a, w0.z, kg[2]); kg[3] = fmaf(a, w0.w, kg[3]);
        kg[4] = fmaf(a, w1.x, kg[4]); kg[5] = fmaf(a, w1.y, kg[5]);
        kg[6] = fmaf(a, w1.z, kg[6]); kg[7] = fmaf(a, w1.w, kg[7]);
    }
    #pragma unroll
    for (int off = 4; off > 0; off >>= 1)
        #pragma unroll
        for (int o = 0; o < 8; o++)
            kg[o] += __shfl_down_sync(0xFFFFFFFFu, kg[o], off, 8);
    if (lane == 0) {
        float dy0 = dm1y[b*2+0], dy1 = dm1y[b*2+1];
        #pragma unroll
        for (int m = 0; m < 4; m++) {
            float k0 = kg[2*m]   + __ldg(&b3[2*m]);
            float k1 = kg[2*m+1] + __ldg(&b3[2*m+1]);
            float pv = prior[b*4+m] + k0*dy0 + k1*dy1;
            post[b*4+m] = pv;
            out_t[b*4+m] = pv;
        }
    }
}

// ---------------- launch ----------------------------------------------------
extern "C" void kernel_launch(void* const* d_in, const int* in_sizes, int n_in,
                              void* d_out, int out_size) {
    const float* y   = (const float*)d_in[0];
    const float* F   = (const float*)d_in[1];
    const float* Hm  = (const float*)d_in[2];
    const float* W1  = (const float*)d_in[3];
    const float* b1  = (const float*)d_in[4];
    const float* Wg  = (const float*)d_in[5];   // [480,600]
    const float* Ug  = (const float*)d_in[6];   // [200,600]
    const float* bg  = (const float*)d_in[7];   // [2,600]
    const float* W2  = (const float*)d_in[8];   // [200,320]
    const float* b2  = (const float*)d_in[9];
    const float* W3  = (const float*)d_in[10];
    const float* b3  = (const float*)d_in[11];
    const float* hn0 = (const float*)d_in[12];
    float* out = (float*)d_out;

    float *gx, *gh, *a2, *hn, *prior, *post, *dm1y;
    __nv_bfloat16 *a1h, *a1l, *hnh, *hnl, *WgTh, *WgTl, *UgTh, *UgTl, *W2Th, *W2Tl;
    cudaGetSymbolAddress((void**)&gx,   g_gx);
    cudaGetSymbolAddress((void**)&gh,   g_gh);
    cudaGetSymbolAddress((void**)&a2,   g_a2);
    cudaGetSymbolAddress((void**)&hn,   g_hn);
    cudaGetSymbolAddress((void**)&prior,g_prior);
    cudaGetSymbolAddress((void**)&post, g_post);
    cudaGetSymbolAddress((void**)&dm1y, g_dm1y);
    cudaGetSymbolAddress((void**)&a1h,  g_a1h);
    cudaGetSymbolAddress((void**)&a1l,  g_a1l);
    cudaGetSymbolAddress((void**)&hnh,  g_hnh);
    cudaGetSymbolAddress((void**)&hnl,  g_hnl);
    cudaGetSymbolAddress((void**)&WgTh, g_WgTh);
    cudaGetSymbolAddress((void**)&WgTl, g_WgTl);
    cudaGetSymbolAddress((void**)&UgTh, g_UgTh);
    cudaGetSymbolAddress((void**)&UgTl, g_UgTl);
    cudaGetSymbolAddress((void**)&W2Th, g_W2Th);
    cudaGetSymbolAddress((void**)&W2Tl, g_W2Tl);

    const int SMEM = 2 * STAGE;     // 61440
    cudaFuncSetAttribute(gemm_mma<false>,
                         cudaFuncAttributeMaxDynamicSharedMemorySize, SMEM);
    cudaFuncSetAttribute(gemm_mma<true>,
                         cudaFuncAttributeMaxDynamicSharedMemorySize, SMEM);

    wsplit_kernel<<<(H1*3*HID + 255)/256, 256>>>(Wg, WgTh, WgTl, H1, 3*HID);
    wsplit_kernel<<<(HID*3*HID + 255)/256, 256>>>(Ug, UgTh, UgTl, HID, 3*HID);
    wsplit_kernel<<<(HID*H2 + 255)/256, 256>>>(W2, W2Th, W2Tl, HID, H2);
    init_kernel<<<(BATCH*HID + 255)/256, 256>>>(hn0, hn, hnh, hnl, prior, post);

    for (int t = 0; t < T_STEPS; t++) {
        const float* hin = hn + (size_t)(t & 1) * BATCH * HID;
        float* hout      = hn + (size_t)((t + 1) & 1) * BATCH * HID;

        feat_a1_kernel<<<BATCH/64, 256>>>(y + (size_t)t*BATCH*NDIM, F, Hm, W1, b1,
                                          post, prior, dm1y, a1h, a1l);

        gemm_mma<false><<<dim3(10, BATCH/128), 256, SMEM>>>(
            a1h, a1l, WgTh, WgTl, bg,         gx, 3*HID, H1);
        gemm_mma<false><<<dim3(10, BATCH/128), 256, SMEM>>>(
            hnh, hnl, UgTh, UgTl, bg + 3*HID, gh, 3*HID, HID);

        gru_gate_kernel<<<(BATCH*HID + 255)/256, 256>>>(gx, gh, hin, hout, hnh, hnl);

        gemm_mma<true><<<dim3(5, BATCH/128), 256, SMEM>>>(
            hnh, hnl, W2Th, W2Tl, b2, a2, H2, HID);

        out_kernel<<<BATCH/32, 256>>>(a2, W3, b3, dm1y, prior, post,
                                      out + (size_t)t*BATCH*MDIM);
    }
}

// round 5
// speedup vs baseline: 2.5583x; 1.3417x over previous
#include <cuda_runtime.h>
#include <cuda_fp16.h>
#include <cstdint>
#include <math.h>

#define T_STEPS 32
#define BATCH   8192
#define MDIM    4
#define NDIM    2
#define H1      480
#define HID     200
#define H2      320

// ---------------- scratch (device globals; no allocation allowed) -----------
__device__ float g_gx  [BATCH * 3 * HID];
__device__ float g_gh  [BATCH * 3 * HID];
__device__ float g_a2  [BATCH * H2];
__device__ float g_hn  [2 * BATCH * HID];
__device__ float g_prior[BATCH * MDIM];
__device__ float g_post [BATCH * MDIM];
__device__ float g_dm1y [BATCH * NDIM];
// fp16 activation planes (single) + weight planes (hi/lo split)
__device__ __half g_a1 [BATCH * H1];
__device__ __half g_hnh[BATCH * HID];
__device__ __half g_WgTh[3*HID*H1],  g_WgTl[3*HID*H1];
__device__ __half g_UgTh[3*HID*HID], g_UgTl[3*HID*HID];
__device__ __half g_W2Th[H2*HID],    g_W2Tl[H2*HID];

// ---------------- PTX helpers ------------------------------------------------
__device__ __forceinline__ uint32_t smem_u32(const void* p) {
    uint32_t a;
    asm("{ .reg .u64 t; cvta.to.shared.u64 t, %1; cvt.u32.u64 %0, t; }" : "=r"(a) : "l"(p));
    return a;
}
__device__ __forceinline__ void cp16(uint32_t dst, const void* src) {
    asm volatile("cp.async.cg.shared.global [%0], [%1], 16;" :: "r"(dst), "l"(src) : "memory");
}
__device__ __forceinline__ void sts_zero16(uint32_t addr) {
    asm volatile("st.shared.v4.b32 [%0], {%1,%1,%1,%1};" :: "r"(addr), "r"(0) : "memory");
}
__device__ __forceinline__ void ldsm4(uint32_t* r, uint32_t addr) {
    asm volatile("ldmatrix.sync.aligned.m8n8.x4.shared.b16 {%0,%1,%2,%3}, [%4];"
                 : "=r"(r[0]), "=r"(r[1]), "=r"(r[2]), "=r"(r[3]) : "r"(addr));
}
__device__ __forceinline__ void mma16816(float* c, const uint32_t* a, uint32_t b0, uint32_t b1) {
    asm volatile("mma.sync.aligned.m16n8k16.row.col.f32.f16.f16.f32 "
                 "{%0,%1,%2,%3}, {%4,%5,%6,%7}, {%8,%9}, {%0,%1,%2,%3};"
                 : "+f"(c[0]), "+f"(c[1]), "+f"(c[2]), "+f"(c[3])
                 : "r"(a[0]), "r"(a[1]), "r"(a[2]), "r"(a[3]), "r"(b0), "r"(b1));
}

// ---------------- split-fp16 HMMA GEMM ---------------------------------------
// C[128 x 64 tile] = A[M x K] @ (Bh+Bl)^T[N x K] + bias, fp32 out.
// A single fp16 plane; B hi+lo fp16 planes -> 2 MMA per K16.
// BK=64, 256 threads, 8 warps (4m x 2n), warp tile 32x32, 2-stage cp.async.
#define ROWB   144                    // 128B data + 16B pad (conflict-free ldmatrix)
#define A_PL   (128 * ROWB)           // 18432
#define B_PL   (64 * ROWB)            // 9216
#define STAGE  (A_PL + 2 * B_PL)      // 36864

template<bool RELU>
__global__ __launch_bounds__(256, 2)
void gemm_mma(const __half* __restrict__ A,
              const __half* __restrict__ Bh, const __half* __restrict__ Bl,
              const float* __restrict__ bias, float* __restrict__ C,
              int Ncols, int K) {
    extern __shared__ char smem[];
    const uint32_t s0 = smem_u32(smem);
    const int tid  = threadIdx.x;
    const int lane = tid & 31, wid = tid >> 5;
    const int wm = (wid & 3) * 32;
    const int wn = (wid >> 2) * 32;
    const int bm = blockIdx.y * 128;
    const int bn = blockIdx.x * 64;

    float acc[2][4][4];
    #pragma unroll
    for (int i = 0; i < 2; i++)
        #pragma unroll
        for (int j = 0; j < 4; j++)
            #pragma unroll
            for (int k = 0; k < 4; k++) acc[i][j][k] = 0.f;

    const int NC = (K + 63) / 64;

    auto load_stage = [&](int s) {
        uint32_t base = s0 + (uint32_t)(s & 1) * STAGE;
        int k0 = s * 64;
        int kc = K - k0; if (kc > 64) kc = 64;
        #pragma unroll
        for (int it = 0; it < 4; it++) {             // A: 128 rows x 8 chunks
            int idx = tid + it * 256;
            int r = idx >> 3, ch = idx & 7;
            uint32_t dst = base + (uint32_t)r * ROWB + (uint32_t)ch * 16;
            if (ch * 8 < kc)
                cp16(dst, A + (size_t)(bm + r) * K + k0 + ch * 8);
            else
                sts_zero16(dst);
        }
        #pragma unroll
        for (int it = 0; it < 4; it++) {             // B: 2 planes x 64 rows x 8 chunks
            int idx = tid + it * 256;
            int plane = idx >> 9, r = (idx >> 3) & 63, ch = idx & 7;
            uint32_t dst = base + A_PL + (uint32_t)plane * B_PL
                         + (uint32_t)r * ROWB + (uint32_t)ch * 16;
            if ((bn + r) < Ncols && ch * 8 < kc)
                cp16(dst, (plane ? Bl : Bh) + (size_t)(bn + r) * K + k0 + ch * 8);
            else
                sts_zero16(dst);
        }
        asm volatile("cp.async.commit_group;" ::: "memory");
    };

    load_stage(0);

    const uint32_t a_lrow = (uint32_t)(lane & 15) * ROWB + (uint32_t)(lane >> 4) * 16;
    const uint32_t b_lrow = (uint32_t)((lane & 7) + ((lane >> 3) & 1) * 8) * ROWB
                          + (uint32_t)(lane >> 4) * 16;

    for (int i = 0; i < NC; i++) {
        if (i + 1 < NC) {
            load_stage(i + 1);
            asm volatile("cp.async.wait_group 1;" ::: "memory");
        } else {
            asm volatile("cp.async.wait_group 0;" ::: "memory");
        }
        __syncthreads();

        uint32_t base = s0 + (uint32_t)(i & 1) * STAGE;
        uint32_t sA  = base;
        uint32_t sBh = base + A_PL, sBl = sBh + B_PL;

        #pragma unroll
        for (int ks = 0; ks < 4; ks++) {
            uint32_t koff = (uint32_t)ks * 32;       // 16 halves = 32B
            uint32_t a[2][4], bh[2][4], bl[2][4];
            #pragma unroll
            for (int fm = 0; fm < 2; fm++)
                ldsm4(a[fm], sA + (uint32_t)(wm + fm * 16) * ROWB + koff + a_lrow);
            #pragma unroll
            for (int np = 0; np < 2; np++) {
                uint32_t ro = (uint32_t)(wn + np * 16) * ROWB + koff + b_lrow;
                ldsm4(bh[np], sBh + ro);
                ldsm4(bl[np], sBl + ro);
            }
            #pragma unroll
            for (int fm = 0; fm < 2; fm++)
                #pragma unroll
                for (int j = 0; j < 4; j++) {
                    int np = j >> 1, sel = j & 1;
                    mma16816(acc[fm][j], a[fm], bh[np][sel], bh[np][sel + 2]);
                    mma16816(acc[fm][j], a[fm], bl[np][sel], bl[np][sel + 2]);
                }
        }
        __syncthreads();
    }

    const int qid = lane >> 2, qt = lane & 3;
    #pragma unroll
    for (int fm = 0; fm < 2; fm++) {
        int row = bm + wm + fm * 16 + qid;
        #pragma unroll
        for (int j = 0; j < 4; j++) {
            int col = bn + wn + j * 8 + qt * 2;
            if (col >= Ncols) continue;
            float b0 = __ldg(&bias[col]), b1 = __ldg(&bias[col + 1]);
            float2 v0 = make_float2(acc[fm][j][0] + b0, acc[fm][j][1] + b1);
            float2 v1 = make_float2(acc[fm][j][2] + b0, acc[fm][j][3] + b1);
            if (RELU) {
                v0.x = fmaxf(v0.x, 0.f); v0.y = fmaxf(v0.y, 0.f);
                v1.x = fmaxf(v1.x, 0.f); v1.y = fmaxf(v1.y, 0.f);
            }
            *(float2*)&C[(size_t)row * Ncols + col]       = v0;
            *(float2*)&C[(size_t)(row + 8) * Ncols + col] = v1;
        }
    }
}

// ---------------- small kernels ---------------------------------------------
__device__ __forceinline__ void wsplit_store(float v, __half* hi, __half* lo, size_t idx) {
    __half h = __float2half_rn(v);
    hi[idx] = h;
    lo[idx] = __float2half_rn(v - __half2float(h));
}

__global__ void init_kernel(const float* __restrict__ hn0, float* __restrict__ hn,
                            __half* __restrict__ hnh,
                            float* __restrict__ prior, float* __restrict__ post) {
    int i = blockIdx.x * blockDim.x + threadIdx.x;
    if (i < BATCH * HID) {
        float v = hn0[i];
        hn[i] = v;
        hnh[i] = __float2half_rn(v);
    }
    if (i < BATCH * MDIM) { prior[i] = 0.f; post[i] = 0.f; }
}

// transpose + split weights: in [K x N] -> planes [N x K]
__global__ void wsplit_kernel(const float* __restrict__ in,
                              __half* __restrict__ oh, __half* __restrict__ ol,
                              int K, int N) {
    int i = blockIdx.x * blockDim.x + threadIdx.x;
    if (i < K * N) {
        int k = i / N, n = i % N;
        wsplit_store(in[i], oh, ol, (size_t)n * K + k);
    }
}

__global__ void feat_a1_kernel(const float* __restrict__ y_t,
                               const float* __restrict__ F, const float* __restrict__ Hm,
                               const float* __restrict__ W1, const float* __restrict__ b1,
                               const float* __restrict__ post, float* __restrict__ prior,
                               float* __restrict__ dm1y_out,
                               __half* __restrict__ a1) {
    __shared__ float feat[64][9];
    int tid = threadIdx.x;
    int b0 = blockIdx.x * 64;
    if (tid < 64) {
        int b = b0 + tid;
        float p[4], pr_old[4];
        #pragma unroll
        for (int m = 0; m < 4; m++) { p[m] = post[b*4+m]; pr_old[m] = prior[b*4+m]; }
        float pn[4];
        #pragma unroll
        for (int i = 0; i < 4; i++) {
            float s = 0.f;
            #pragma unroll
            for (int j = 0; j < 4; j++) s += __ldg(&F[i*4+j]) * p[j];
            pn[i] = s;
        }
        float my[2];
        #pragma unroll
        for (int i = 0; i < 2; i++) {
            float s = 0.f;
            #pragma unroll
            for (int j = 0; j < 4; j++) s += __ldg(&Hm[i*4+j]) * pn[j];
            my[i] = s;
        }
        float dy0 = y_t[b*2+0] - my[0];
        float dy1 = y_t[b*2+1] - my[1];
        dm1y_out[b*2+0] = dy0;
        dm1y_out[b*2+1] = dy1;
        float inv_y = rsqrtf(fmaxf(dy0*dy0 + dy1*dy1, 1e-12f));
        feat[tid][0] = dy0*inv_y; feat[tid][1] = dy1*inv_y;
        feat[tid][2] = dy0*inv_y; feat[tid][3] = dy1*inv_y;
        float d[4], s2 = 0.f;
        #pragma unroll
        for (int m = 0; m < 4; m++) { d[m] = p[m] - pr_old[m]; s2 += d[m]*d[m]; }
        float inv_x = rsqrtf(fmaxf(s2, 1e-12f));
        #pragma unroll
        for (int m = 0; m < 4; m++) feat[tid][4+m] = d[m]*inv_x;
        #pragma unroll
        for (int m = 0; m < 4; m++) prior[b*4+m] = pn[m];
    }
    __syncthreads();
    for (int idx = tid; idx < 64 * H1; idx += 256) {
        int r = idx / H1, c = idx % H1;
        float s = __ldg(&b1[c]);
        #pragma unroll
        for (int k = 0; k < 8; k++) s += feat[r][k] * __ldg(&W1[k*H1 + c]);
        a1[(size_t)(b0 + r) * H1 + c] = __float2half_rn(fmaxf(s, 0.f));
    }
}

__global__ void gru_gate_kernel(const float* __restrict__ Gx, const float* __restrict__ Gh,
                                const float* __restrict__ h_in, float* __restrict__ h_out,
                                __half* __restrict__ hnh) {
    int idx = blockIdx.x * blockDim.x + threadIdx.x;
    if (idx >= BATCH * HID) return;
    int b = idx / HID, j = idx % HID;
    const float* gx = Gx + (size_t)b * 3 * HID;
    const float* gh = Gh + (size_t)b * 3 * HID;
    float z = 1.f / (1.f + __expf(-(gx[j]       + gh[j])));
    float r = 1.f / (1.f + __expf(-(gx[j + HID] + gh[j + HID])));
    float hc = tanhf(gx[j + 2*HID] + r * gh[j + 2*HID]);
    float h = h_in[idx];
    float v = z * h + (1.f - z) * hc;
    h_out[idx] = v;
    hnh[idx] = __float2half_rn(v);
}

__global__ void out_kernel(const float* __restrict__ a2, const float* __restrict__ W3,
                           const float* __restrict__ b3, const float* __restrict__ dm1y,
                           const float* __restrict__ prior, float* __restrict__ post,
                           float* __restrict__ out_t) {
    int tid = threadIdx.x;
    int lane = tid & 7;
    int b = blockIdx.x * 32 + (tid >> 3);
    float kg[8];
    #pragma unroll
    for (int o = 0; o < 8; o++) kg[o] = 0.f;
    const float* arow = a2 + (size_t)b * H2;
    for (int k = lane; k < H2; k += 8) {
        float a = arow[k];
        float4 w0 = *(const float4*)(W3 + k*8);
        float4 w1 = *(const float4*)(W3 + k*8 + 4);
        kg[0] = fmaf(a, w0.x, kg[0]); kg[1] = fmaf(a, w0.y, kg[1]);
        kg[2] = fmaf(a, w0.z, kg[2]); kg[3] = fmaf(a, w0.w, kg[3]);
        kg[4] = fmaf(a, w1.x, kg[4]); kg[5] = fmaf(a, w1.y, kg[5]);
        kg[6] = fmaf(a, w1.z, kg[6]); kg[7] = fmaf(a, w1.w, kg[7]);
    }
    #pragma unroll
    for (int off = 4; off > 0; off >>= 1)
        #pragma unroll
        for (int o = 0; o < 8; o++)
            kg[o] += __shfl_down_sync(0xFFFFFFFFu, kg[o], off, 8);
    if (lane == 0) {
        float dy0 = dm1y[b*2+0], dy1 = dm1y[b*2+1];
        #pragma unroll
        for (int m = 0; m < 4; m++) {
            float k0 = kg[2*m]   + __ldg(&b3[2*m]);
            float k1 = kg[2*m+1] + __ldg(&b3[2*m+1]);
            float pv = prior[b*4+m] + k0*dy0 + k1*dy1;
            post[b*4+m] = pv;
            out_t[b*4+m] = pv;
        }
    }
}

// ---------------- launch ----------------------------------------------------
extern "C" void kernel_launch(void* const* d_in, const int* in_sizes, int n_in,
                              void* d_out, int out_size) {
    const float* y   = (const float*)d_in[0];
    const float* F   = (const float*)d_in[1];
    const float* Hm  = (const float*)d_in[2];
    const float* W1  = (const float*)d_in[3];
    const float* b1  = (const float*)d_in[4];
    const float* Wg  = (const float*)d_in[5];   // [480,600]
    const float* Ug  = (const float*)d_in[6];   // [200,600]
    const float* bg  = (const float*)d_in[7];   // [2,600]
    const float* W2  = (const float*)d_in[8];   // [200,320]
    const float* b2  = (const float*)d_in[9];
    const float* W3  = (const float*)d_in[10];
    const float* b3  = (const float*)d_in[11];
    const float* hn0 = (const float*)d_in[12];
    float* out = (float*)d_out;

    float *gx, *gh, *a2, *hn, *prior, *post, *dm1y;
    __half *a1, *hnh, *WgTh, *WgTl, *UgTh, *UgTl, *W2Th, *W2Tl;
    cudaGetSymbolAddress((void**)&gx,   g_gx);
    cudaGetSymbolAddress((void**)&gh,   g_gh);
    cudaGetSymbolAddress((void**)&a2,   g_a2);
    cudaGetSymbolAddress((void**)&hn,   g_hn);
    cudaGetSymbolAddress((void**)&prior,g_prior);
    cudaGetSymbolAddress((void**)&post, g_post);
    cudaGetSymbolAddress((void**)&dm1y, g_dm1y);
    cudaGetSymbolAddress((void**)&a1,   g_a1);
    cudaGetSymbolAddress((void**)&hnh,  g_hnh);
    cudaGetSymbolAddress((void**)&WgTh, g_WgTh);
    cudaGetSymbolAddress((void**)&WgTl, g_WgTl);
    cudaGetSymbolAddress((void**)&UgTh, g_UgTh);
    cudaGetSymbolAddress((void**)&UgTl, g_UgTl);
    cudaGetSymbolAddress((void**)&W2Th, g_W2Th);
    cudaGetSymbolAddress((void**)&W2Tl, g_W2Tl);

    const int SMEM = 2 * STAGE;     // 73728
    cudaFuncSetAttribute(gemm_mma<false>,
                         cudaFuncAttributeMaxDynamicSharedMemorySize, SMEM);
    cudaFuncSetAttribute(gemm_mma<true>,
                         cudaFuncAttributeMaxDynamicSharedMemorySize, SMEM);

    wsplit_kernel<<<(H1*3*HID + 255)/256, 256>>>(Wg, WgTh, WgTl, H1, 3*HID);
    wsplit_kernel<<<(HID*3*HID + 255)/256, 256>>>(Ug, UgTh, UgTl, HID, 3*HID);
    wsplit_kernel<<<(HID*H2 + 255)/256, 256>>>(W2, W2Th, W2Tl, HID, H2);
    init_kernel<<<(BATCH*HID + 255)/256, 256>>>(hn0, hn, hnh, prior, post);

    for (int t = 0; t < T_STEPS; t++) {
        const float* hin = hn + (size_t)(t & 1) * BATCH * HID;
        float* hout      = hn + (size_t)((t + 1) & 1) * BATCH * HID;

        feat_a1_kernel<<<BATCH/64, 256>>>(y + (size_t)t*BATCH*NDIM, F, Hm, W1, b1,
                                          post, prior, dm1y, a1);

        gemm_mma<false><<<dim3(10, BATCH/128), 256, SMEM>>>(
            a1, WgTh, WgTl, bg,          gx, 3*HID, H1);
        gemm_mma<false><<<dim3(10, BATCH/128), 256, SMEM>>>(
            hnh, UgTh, UgTl, bg + 3*HID, gh, 3*HID, HID);

        gru_gate_kernel<<<(BATCH*HID + 255)/256, 256>>>(gx, gh, hin, hout, hnh);

        gemm_mma<true><<<dim3(5, BATCH/128), 256, SMEM>>>(
            hnh, W2Th, W2Tl, b2, a2, H2, HID);

        out_kernel<<<BATCH/32, 256>>>(a2, W3, b3, dm1y, prior, post,
                                      out + (size_t)t*BATCH*MDIM);
    }
}